// round 12
// baseline (speedup 1.0000x reference)
#include <cuda_runtime.h>
#include <cuda_fp16.h>

#define NN 10000
#define GG 64
#define HID 128
#define OUTC 10
#define BN_EPS 1e-5f
#define EE_MAX 640000
#define NH 16384   // padded histogram length (entries >= NN stay zero forever)

// ---------------- scratch (device globals) ----------------
__device__ int   d_hist[NH];
__device__ int   d_off[NN];
__device__ int   d_cur[NN];
__device__ int   d_rows[EE_MAX];
__device__ uint2 d_xh[NN * HID / 4];    // x as fp16 (4 halves per uint2)
__device__ uint2 d_hh[NN * HID / 4];    // h (post-GIN relu) as fp16
__device__ float d_s[NN];
__device__ float d_w[NN];               // s[i] * sum_{j in CSR[i]} s[j]
__device__ float d_colsum[HID];
__device__ float d_colsum2[HID];
__device__ float d_scale[HID];
__device__ float d_shift[HID];
__device__ float d_hg[GG * HID];
__device__ unsigned d_ticket[4];        // zero-init; atomicInc wraps (graph-replay safe)
__device__ int   d_flag[4];             // BN-ready / s-ready flags per layer (reset each call)

__device__ __forceinline__ void f4acc(float4& a, const float4 v) {
    a.x += v.x; a.y += v.y; a.z += v.z; a.w += v.w;
}
__device__ __forceinline__ void f4fma(float4& a, const float4 v, float s) {
    a.x += v.x * s; a.y += v.y * s; a.z += v.z * s; a.w += v.w * s;
}
__device__ __forceinline__ float4 h4tof4(const uint2 u) {
    float2 f01 = __half22float2(*(const __half2*)&u.x);
    float2 f23 = __half22float2(*(const __half2*)&u.y);
    return make_float4(f01.x, f01.y, f23.x, f23.y);
}

// ---------------- init: zero scratch + convert x to fp16 ----------------
__global__ void init_kernel(const float* __restrict__ x) {
    int i = blockIdx.x * blockDim.x + threadIdx.x;
    if (i < NN * HID / 2) {
        float2 f = ((const float2*)x)[i];
        ((__half2*)d_xh)[i] = __floats2half2_rn(f.x, f.y);
    }
    if (i < NN) d_hist[i] = 0;
    if (i < HID) { d_colsum[i] = 0.f; d_colsum2[i] = 0.f; }
    if (i < GG * HID) d_hg[i] = 0.f;
    if (i < 4) d_flag[i] = 0;
}

// edge_index int32: ei[0..E)=row, ei[E..2E)=col
__global__ void hist_kernel(const int* __restrict__ ei, int E) {
    int e = (blockIdx.x * blockDim.x + threadIdx.x) * 4;
    if (e + 4 <= E) {
        int c0 = ei[E + e], c1 = ei[E + e + 1], c2 = ei[E + e + 2], c3 = ei[E + e + 3];
        atomicAdd(&d_hist[c0], 1);
        atomicAdd(&d_hist[c1], 1);
        atomicAdd(&d_hist[c2], 1);
        atomicAdd(&d_hist[c3], 1);
    } else {
        for (; e < E; e++) atomicAdd(&d_hist[ei[E + e]], 1);
    }
}

// single-block scan, warp-shuffle based
__global__ void scan_kernel() {
    __shared__ int wsum[32];
    const int CH = NH / 1024;  // 16
    int tid = threadIdx.x;
    int lane = tid & 31, wid = tid >> 5;
    int local[CH];
    int4 raw[CH / 4];
#pragma unroll
    for (int q = 0; q < CH / 4; q++) raw[q] = ((const int4*)d_hist)[tid * (CH / 4) + q];
#pragma unroll
    for (int q = 0; q < CH / 4; q++) {
        local[q * 4 + 0] = raw[q].x;
        local[q * 4 + 1] = raw[q].y;
        local[q * 4 + 2] = raw[q].z;
        local[q * 4 + 3] = raw[q].w;
    }
    int tot = 0;
#pragma unroll
    for (int j = 0; j < CH; j++) tot += local[j];
    int inc = tot;
#pragma unroll
    for (int o = 1; o < 32; o <<= 1) {
        int v = __shfl_up_sync(0xffffffff, inc, o);
        if (lane >= o) inc += v;
    }
    if (lane == 31) wsum[wid] = inc;
    __syncthreads();
    if (wid == 0) {
        int v = wsum[lane];
        int iv = v;
#pragma unroll
        for (int o = 1; o < 32; o <<= 1) {
            int u = __shfl_up_sync(0xffffffff, iv, o);
            if (lane >= o) iv += u;
        }
        wsum[lane] = iv - v;
    }
    __syncthreads();
    int run = wsum[wid] + (inc - tot);
    int base = tid * CH;
#pragma unroll
    for (int j = 0; j < CH; j++) {
        int idx = base + j;
        if (idx < NN) {
            d_off[idx] = run;
            d_cur[idx] = run;
        }
        run += local[j];
    }
}

__global__ void scatter_kernel(const int* __restrict__ ei, int E) {
    int e = (blockIdx.x * blockDim.x + threadIdx.x) * 4;
    if (e + 4 <= E) {
        int c0 = ei[E + e], c1 = ei[E + e + 1], c2 = ei[E + e + 2], c3 = ei[E + e + 3];
        int r0 = ei[e], r1 = ei[e + 1], r2 = ei[e + 2], r3 = ei[e + 3];
        int p0 = atomicAdd(&d_cur[c0], 1);
        int p1 = atomicAdd(&d_cur[c1], 1);
        int p2 = atomicAdd(&d_cur[c2], 1);
        int p3 = atomicAdd(&d_cur[c3], 1);
        d_rows[p0] = r0;
        d_rows[p1] = r1;
        d_rows[p2] = r2;
        d_rows[p3] = r3;
    } else {
        for (; e < E; e++) {
            int p = atomicAdd(&d_cur[ei[E + e]], 1);
            d_rows[p] = ei[e];
        }
    }
}

// ================= mega layer kernel =================
// Phase A: aggregate this block's 64 node rows into As (warp-per-node fp16 gather)
// Phase B: y = agg @ W1 + b1 -> BN stats -> grid barrier -> relu(bn(y)) @ W2 + b2 -> relu
//          -> fp16 d_hh + attention score d_s
// Phase C: grid barrier -> per-node w (LAYER 0) or pooled atomicAdd into hg (LAYER 1)
// 157 blocks, __launch_bounds__(256,2) guarantees full co-residency for the spins.
template<int LAYER>
__global__ void __launch_bounds__(256, 2)
mega_kernel(const float* __restrict__ W1, const float* __restrict__ b1,
            const float* __restrict__ g, const float* __restrict__ be, float invn,
            const float* __restrict__ W2, const float* __restrict__ b2,
            const float* __restrict__ aw, const float* __restrict__ ab,
            const int* __restrict__ batch) {
    __shared__ float As[64][HID];   // 32KB: agg tile, then y' tile
    __shared__ float Bs[32][HID];   // 16KB: W chunks / reduction scratch
    int tid = threadIdx.x;
    int tx = tid & 15, ty = tid >> 4;
    int wid = tid >> 5, lane = tid & 31;
    int row0 = blockIdx.x * 64;
    const int TICK = LAYER * 2;

    // ---- Phase A: aggregate 64 rows into As ----
    const uint2* base = (LAYER == 0) ? d_xh : d_hh;
#pragma unroll
    for (int r = wid; r < 64; r += 8) {
        int node = row0 + r;
        float4 a0 = make_float4(0.f, 0.f, 0.f, 0.f);
        float4 a1 = a0, a2 = a0, a3 = a0;
        if (node < NN) {
            int start = d_off[node];
            int deg = d_hist[node];
            float ws = (LAYER == 0) ? 1.f : d_w[node];
            f4fma(a0, h4tof4(base[node * 32 + lane]), ws);   // self
            int e = 0;
            for (; e + 4 <= deg; e += 4) {
                int i0 = d_rows[start + e + 0];
                int i1 = d_rows[start + e + 1];
                int i2 = d_rows[start + e + 2];
                int i3 = d_rows[start + e + 3];
                uint2 u0 = base[i0 * 32 + lane];
                uint2 u1 = base[i1 * 32 + lane];
                uint2 u2 = base[i2 * 32 + lane];
                uint2 u3 = base[i3 * 32 + lane];
                float w0 = (LAYER == 0) ? 1.f : d_w[i0];
                float w1 = (LAYER == 0) ? 1.f : d_w[i1];
                float w2 = (LAYER == 0) ? 1.f : d_w[i2];
                float w3 = (LAYER == 0) ? 1.f : d_w[i3];
                f4fma(a0, h4tof4(u0), w0);
                f4fma(a1, h4tof4(u1), w1);
                f4fma(a2, h4tof4(u2), w2);
                f4fma(a3, h4tof4(u3), w3);
            }
            for (; e < deg; e++) {
                int i0 = d_rows[start + e];
                float w0 = (LAYER == 0) ? 1.f : d_w[i0];
                f4fma(a0, h4tof4(base[i0 * 32 + lane]), w0);
            }
            f4acc(a0, a1);
            f4acc(a2, a3);
            f4acc(a0, a2);
        }
        *(float4*)&As[r][lane * 4] = a0;
    }
    __syncthreads();

    // ---- Phase B1: y = agg @ W1 + b1 ----
    float acc[4][8];
    {
        float bj[8];
#pragma unroll
        for (int jj = 0; jj < 8; jj++) bj[jj] = b1[tx * 8 + jj];
#pragma unroll
        for (int ii = 0; ii < 4; ii++)
#pragma unroll
            for (int jj = 0; jj < 8; jj++) acc[ii][jj] = bj[jj];
    }
#pragma unroll
    for (int kc = 0; kc < 4; kc++) {
        if (kc) __syncthreads();
#pragma unroll
        for (int l = 0; l < 4; l++) {
            int fid = tid + l * 256;
            int r = fid >> 5, c4 = fid & 31;
            *(float4*)&Bs[r][c4 * 4] = *(const float4*)(W1 + (size_t)(kc * 32 + r) * HID + c4 * 4);
        }
        __syncthreads();
#pragma unroll 4
        for (int kk = 0; kk < 32; kk++) {
            int k = kc * 32 + kk;
            float aa[4];
#pragma unroll
            for (int ii = 0; ii < 4; ii++) aa[ii] = As[ty * 4 + ii][k];
            float4 b0 = *(const float4*)&Bs[kk][tx * 8];
            float4 b1v = *(const float4*)&Bs[kk][tx * 8 + 4];
            float bb[8] = {b0.x, b0.y, b0.z, b0.w, b1v.x, b1v.y, b1v.z, b1v.w};
#pragma unroll
            for (int ii = 0; ii < 4; ii++)
#pragma unroll
                for (int jj = 0; jj < 8; jj++) acc[ii][jj] += aa[ii] * bb[jj];
        }
    }

    // ---- BN stats ----
    {
        float p[8], q[8];
#pragma unroll
        for (int jj = 0; jj < 8; jj++) { p[jj] = 0.f; q[jj] = 0.f; }
#pragma unroll
        for (int ii = 0; ii < 4; ii++) {
            int r = row0 + ty * 4 + ii;
            if (r < NN) {
#pragma unroll
                for (int jj = 0; jj < 8; jj++) {
                    float v = acc[ii][jj];
                    p[jj] += v;
                    q[jj] += v * v;
                }
            }
        }
        float* red = &Bs[0][0];
        __syncthreads();
#pragma unroll
        for (int jj = 0; jj < 8; jj++) red[ty * HID + tx * 8 + jj] = p[jj];
        __syncthreads();
        if (tid < HID) {
            float sv = 0.f;
#pragma unroll
            for (int t = 0; t < 16; t++) sv += red[t * HID + tid];
            atomicAdd(&d_colsum[tid], sv);
        }
        __syncthreads();
#pragma unroll
        for (int jj = 0; jj < 8; jj++) red[ty * HID + tx * 8 + jj] = q[jj];
        __syncthreads();
        if (tid < HID) {
            float sv = 0.f;
#pragma unroll
            for (int t = 0; t < 16; t++) sv += red[t * HID + tid];
            atomicAdd(&d_colsum2[tid], sv);
        }
    }

    // ---- grid barrier 1: BN scale/shift ----
    __threadfence();
    __syncthreads();
    if (tid == 0) {
        unsigned t = atomicInc(&d_ticket[TICK], gridDim.x - 1);
        *(int*)&Bs[0][0] = (t == gridDim.x - 1);
    }
    __syncthreads();
    if (*(int*)&Bs[0][0]) {
        if (tid < HID) {
            float m = d_colsum[tid] * invn;
            float var = d_colsum2[tid] * invn - m * m;
            float rs = rsqrtf(var + BN_EPS);
            float sc = g[tid] * rs;
            d_scale[tid] = sc;
            d_shift[tid] = be[tid] - m * sc;
            d_colsum[tid] = 0.f;
            d_colsum2[tid] = 0.f;
        }
        __syncthreads();
        if (tid == 0) {
            __threadfence();
            atomicExch(&d_flag[TICK], 1);
        }
    }
    if (tid == 0) {
        while (atomicAdd(&d_flag[TICK], 0) == 0) __nanosleep(64);
    }
    __syncthreads();
    __threadfence();

    // ---- apply BN+relu, stage y' into As ----
    {
        float scj[8], shj[8];
#pragma unroll
        for (int jj = 0; jj < 8; jj++) {
            scj[jj] = d_scale[tx * 8 + jj];
            shj[jj] = d_shift[tx * 8 + jj];
        }
        __syncthreads();
#pragma unroll
        for (int ii = 0; ii < 4; ii++)
#pragma unroll
            for (int jj = 0; jj < 8; jj++)
                As[ty * 4 + ii][tx * 8 + jj] = fmaxf(acc[ii][jj] * scj[jj] + shj[jj], 0.f);
    }
    float awj[8];
    {
        float bj[8];
#pragma unroll
        for (int jj = 0; jj < 8; jj++) { bj[jj] = b2[tx * 8 + jj]; awj[jj] = aw[tx * 8 + jj]; }
#pragma unroll
        for (int ii = 0; ii < 4; ii++)
#pragma unroll
            for (int jj = 0; jj < 8; jj++) acc[ii][jj] = bj[jj];
    }

    // ---- Phase B2: h = y' @ W2 + b2 ----
#pragma unroll
    for (int kc = 0; kc < 4; kc++) {
        __syncthreads();
#pragma unroll
        for (int l = 0; l < 4; l++) {
            int fid = tid + l * 256;
            int r = fid >> 5, c4 = fid & 31;
            *(float4*)&Bs[r][c4 * 4] = *(const float4*)(W2 + (size_t)(kc * 32 + r) * HID + c4 * 4);
        }
        __syncthreads();
#pragma unroll 4
        for (int kk = 0; kk < 32; kk++) {
            int k = kc * 32 + kk;
            float aa[4];
#pragma unroll
            for (int ii = 0; ii < 4; ii++) aa[ii] = As[ty * 4 + ii][k];
            float4 b0 = *(const float4*)&Bs[kk][tx * 8];
            float4 b1v = *(const float4*)&Bs[kk][tx * 8 + 4];
            float bb[8] = {b0.x, b0.y, b0.z, b0.w, b1v.x, b1v.y, b1v.z, b1v.w};
#pragma unroll
            for (int ii = 0; ii < 4; ii++)
#pragma unroll
                for (int jj = 0; jj < 8; jj++) acc[ii][jj] += aa[ii] * bb[jj];
        }
    }

    // ---- epilogue: relu -> fp16 h store + attention score s ----
    float sp[4] = {0.f, 0.f, 0.f, 0.f};
#pragma unroll
    for (int ii = 0; ii < 4; ii++) {
        int r = row0 + ty * 4 + ii;
        if (r < NN) {
            float v[8];
#pragma unroll
            for (int jj = 0; jj < 8; jj++) {
                v[jj] = fmaxf(acc[ii][jj], 0.f);
                sp[ii] += v[jj] * awj[jj];
            }
            uint2 u0, u1;
            *(__half2*)&u0.x = __floats2half2_rn(v[0], v[1]);
            *(__half2*)&u0.y = __floats2half2_rn(v[2], v[3]);
            *(__half2*)&u1.x = __floats2half2_rn(v[4], v[5]);
            *(__half2*)&u1.y = __floats2half2_rn(v[6], v[7]);
            d_hh[r * 32 + tx * 2 + 0] = u0;
            d_hh[r * 32 + tx * 2 + 1] = u1;
        }
    }
    {
        float* red = &Bs[0][0];   // 64*16 floats
        __syncthreads();
#pragma unroll
        for (int ii = 0; ii < 4; ii++) red[(ty * 4 + ii) * 16 + tx] = sp[ii];
        __syncthreads();
        if (tid < 64) {
            float v = 0.f;
#pragma unroll
            for (int t = 0; t < 16; t++) v += red[t + tid * 16];
            int r = row0 + tid;
            if (r < NN) d_s[r] = 1.f / (1.f + expf(-(v + ab[0])));
        }
    }

    // ---- grid barrier 2: all s written ----
    __threadfence();
    __syncthreads();
    if (tid == 0) {
        unsigned t = atomicInc(&d_ticket[TICK + 1], gridDim.x - 1);
        *(int*)&Bs[0][0] = (t == gridDim.x - 1);
    }
    __syncthreads();
    if (*(int*)&Bs[0][0]) {
        if (tid == 0) {
            __threadfence();
            atomicExch(&d_flag[TICK + 1], 1);
        }
    }
    if (tid == 0) {
        while (atomicAdd(&d_flag[TICK + 1], 0) == 0) __nanosleep(64);
    }
    __syncthreads();
    __threadfence();

    // ---- Phase C: per-node edge-sum of s, then w (layer 0) or pool (layer 1) ----
#pragma unroll
    for (int r = wid; r < 64; r += 8) {
        int node = row0 + r;
        if (node >= NN) continue;
        int start = d_off[node];
        int deg = d_hist[node];
        float t = 0.f;
        for (int e = lane; e < deg; e += 32) t += d_s[d_rows[start + e]];
#pragma unroll
        for (int o = 16; o; o >>= 1) t += __shfl_xor_sync(0xffffffff, t, o);
        float w = d_s[node] * t;
        if (LAYER == 0) {
            if (lane == 0) d_w[node] = w;
        } else {
            float4 hv = h4tof4(d_hh[node * 32 + lane]);
            int b = batch[node];
            float* dst = &d_hg[b * HID + lane * 4];
            atomicAdd(dst + 0, hv.x * w);
            atomicAdd(dst + 1, hv.y * w);
            atomicAdd(dst + 2, hv.z * w);
            atomicAdd(dst + 3, hv.w * w);
        }
    }
}

// ---------------- head: MLP(hg) + log_softmax, single block ----------------
__global__ void __launch_bounds__(256)
head_kernel(const float* __restrict__ w1, const float* __restrict__ b1,
            const float* __restrict__ g, const float* __restrict__ be,
            const float* __restrict__ w2, const float* __restrict__ b2,
            float* __restrict__ out) {
    __shared__ float ys[GG][HID];
    __shared__ float sc[HID], sh[HID];
    __shared__ float logits[GG * OUTC];
    int tid = threadIdx.x;

#pragma unroll
    for (int l = 0; l < 8; l++) {
        int idx = tid + l * 256;
        ((float4*)&ys[0][0])[idx] = ((const float4*)d_hg)[idx];
    }
    __syncthreads();

    int row = tid >> 2;
    int c0 = (tid & 3) * 32;
    float acc[32];
#pragma unroll
    for (int j = 0; j < 32; j++) acc[j] = b1[c0 + j];
    for (int k = 0; k < HID; k++) {
        float a = ys[row][k];
#pragma unroll
        for (int j4 = 0; j4 < 8; j4++) {
            float4 w = *(const float4*)(w1 + (size_t)k * HID + c0 + j4 * 4);
            acc[j4 * 4 + 0] += a * w.x;
            acc[j4 * 4 + 1] += a * w.y;
            acc[j4 * 4 + 2] += a * w.z;
            acc[j4 * 4 + 3] += a * w.w;
        }
    }
    __syncthreads();
#pragma unroll
    for (int j = 0; j < 32; j++) ys[row][c0 + j] = acc[j];
    __syncthreads();

    if (tid < HID) {
        float s1 = 0.f, s2 = 0.f;
#pragma unroll 8
        for (int r = 0; r < GG; r++) {
            float v = ys[r][tid];
            s1 += v;
            s2 += v * v;
        }
        float m = s1 / GG;
        float var = s2 / GG - m * m;
        float rs = rsqrtf(var + BN_EPS);
        float scale = g[tid] * rs;
        sc[tid] = scale;
        sh[tid] = be[tid] - m * scale;
    }
    __syncthreads();

    for (int idx = tid; idx < GG * OUTC; idx += 256) {
        int gr = idx / OUTC, o = idx - gr * OUTC;
        float v = b2[o];
        for (int k = 0; k < HID; k++) {
            float hv = fmaxf(ys[gr][k] * sc[k] + sh[k], 0.f);
            v += hv * w2[k * OUTC + o];
        }
        logits[idx] = v;
    }
    __syncthreads();

    if (tid < GG) {
        float mx = -1e30f;
#pragma unroll
        for (int o = 0; o < OUTC; o++) mx = fmaxf(mx, logits[tid * OUTC + o]);
        float sum = 0.f;
#pragma unroll
        for (int o = 0; o < OUTC; o++) sum += expf(logits[tid * OUTC + o] - mx);
        float ls = mx + logf(sum);
#pragma unroll
        for (int o = 0; o < OUTC; o++) out[tid * OUTC + o] = logits[tid * OUTC + o] - ls;
    }
}

// ---------------- host launch ----------------
extern "C" void kernel_launch(void* const* d_in, const int* in_sizes, int n_in,
                              void* d_out, int out_size) {
    const float* x = (const float*)d_in[0];
    const int* ei = (const int*)d_in[1];
    const int* batch = (const int*)d_in[2];
    const float* c1_w1 = (const float*)d_in[3];
    const float* c1_b1 = (const float*)d_in[4];
    const float* c1_g  = (const float*)d_in[5];
    const float* c1_be = (const float*)d_in[6];
    const float* c1_w2 = (const float*)d_in[7];
    const float* c1_b2 = (const float*)d_in[8];
    const float* a1_w  = (const float*)d_in[9];
    const float* a1_b  = (const float*)d_in[10];
    const float* c2_w1 = (const float*)d_in[11];
    const float* c2_b1 = (const float*)d_in[12];
    const float* c2_g  = (const float*)d_in[13];
    const float* c2_be = (const float*)d_in[14];
    const float* c2_w2 = (const float*)d_in[15];
    const float* c2_b2 = (const float*)d_in[16];
    const float* a2_w  = (const float*)d_in[17];
    const float* a2_b  = (const float*)d_in[18];
    const float* l_w1  = (const float*)d_in[19];
    const float* l_b1  = (const float*)d_in[20];
    const float* l_g   = (const float*)d_in[21];
    const float* l_be  = (const float*)d_in[22];
    const float* l_w2  = (const float*)d_in[23];
    const float* l_b2  = (const float*)d_in[24];
    float* out = (float*)d_out;

    int E = in_sizes[1] / 2;

    const int GEMM_GRID = (NN + 63) / 64;   // 157 (<= 2 blocks/SM * 148 SMs)
    const int E4_GRID = ((E + 3) / 4 + 255) / 256;

    // init + CSR build
    init_kernel<<<(NN * HID / 2 + 255) / 256, 256>>>(x);
    hist_kernel<<<E4_GRID, 256>>>(ei, E);
    scan_kernel<<<1, 1024>>>();
    scatter_kernel<<<E4_GRID, 256>>>(ei, E);

    // GIN layer 1 + 2, each fully fused (agg + MLP + BN + attn + tst/pool)
    mega_kernel<0><<<GEMM_GRID, 256>>>(c1_w1, c1_b1, c1_g, c1_be, 1.f / NN,
                                       c1_w2, c1_b2, a1_w, a1_b, batch);
    mega_kernel<1><<<GEMM_GRID, 256>>>(c2_w1, c2_b1, c2_g, c2_be, 1.f / NN,
                                       c2_w2, c2_b2, a2_w, a2_b, batch);

    // head
    head_kernel<<<1, 256>>>(l_w1, l_b1, l_g, l_be, l_w2, l_b2, out);
}

// round 14
// speedup vs baseline: 1.1204x; 1.1204x over previous
#include <cuda_runtime.h>
#include <cuda_fp16.h>

#define NN 10000
#define GG 64
#define HID 128
#define OUTC 10
#define BN_EPS 1e-5f
#define EE_MAX 640000
#define NH 16384   // padded histogram length (entries >= NN stay zero forever)

// ---------------- scratch (device globals) ----------------
__device__ int   d_hist[NH];
__device__ int   d_off[NN];
__device__ int   d_cur[NN];
__device__ unsigned short d_rows[EE_MAX];   // node ids < 10000 fit in u16
__device__ uint2 d_xh[NN * HID / 4];    // x as fp16 (4 halves per uint2)
__device__ uint2 d_hh[NN * HID / 4];    // h (post-GIN relu) as fp16
__device__ float d_z[NN * HID];
__device__ float d_s[NN];
__device__ float d_w[NN];               // s[i] * sum_{j in CSR[i]} s[j]
__device__ float d_colsum[HID];
__device__ float d_colsum2[HID];
__device__ float d_scale[HID];
__device__ float d_shift[HID];
__device__ float d_hg[GG * HID];
__device__ unsigned d_ticket;           // zero-init; atomicInc wraps (graph-replay safe)
__device__ int   d_flag[2];             // per-layer BN-ready flag (reset each call)

__device__ __forceinline__ void f4acc(float4& a, const float4 v) {
    a.x += v.x; a.y += v.y; a.z += v.z; a.w += v.w;
}
__device__ __forceinline__ void f4fma(float4& a, const float4 v, float s) {
    a.x += v.x * s; a.y += v.y * s; a.z += v.z * s; a.w += v.w * s;
}
__device__ __forceinline__ float4 h4tof4(const uint2 u) {
    float2 f01 = __half22float2(*(const __half2*)&u.x);
    float2 f23 = __half22float2(*(const __half2*)&u.y);
    return make_float4(f01.x, f01.y, f23.x, f23.y);
}

// ---------------- init: zero scratch + convert x to fp16 ----------------
__global__ void init_kernel(const float* __restrict__ x) {
    int i = blockIdx.x * blockDim.x + threadIdx.x;
    if (i < NN * HID / 2) {
        float2 f = ((const float2*)x)[i];
        ((__half2*)d_xh)[i] = __floats2half2_rn(f.x, f.y);
    }
    if (i < NN) d_hist[i] = 0;
    if (i < HID) { d_colsum[i] = 0.f; d_colsum2[i] = 0.f; }
    if (i < GG * HID) d_hg[i] = 0.f;
    if (i < 2) d_flag[i] = 0;
}

// edge_index int32: ei[0..E)=row, ei[E..2E)=col
__global__ void hist_kernel(const int* __restrict__ ei, int E) {
    int e = (blockIdx.x * blockDim.x + threadIdx.x) * 4;
    if (e + 4 <= E) {
        int c0 = ei[E + e], c1 = ei[E + e + 1], c2 = ei[E + e + 2], c3 = ei[E + e + 3];
        atomicAdd(&d_hist[c0], 1);
        atomicAdd(&d_hist[c1], 1);
        atomicAdd(&d_hist[c2], 1);
        atomicAdd(&d_hist[c3], 1);
    } else {
        for (; e < E; e++) atomicAdd(&d_hist[ei[E + e]], 1);
    }
}

// single-block scan, warp-shuffle based
__global__ void scan_kernel() {
    __shared__ int wsum[32];
    const int CH = NH / 1024;  // 16
    int tid = threadIdx.x;
    int lane = tid & 31, wid = tid >> 5;
    int local[CH];
    int4 raw[CH / 4];
#pragma unroll
    for (int q = 0; q < CH / 4; q++) raw[q] = ((const int4*)d_hist)[tid * (CH / 4) + q];
#pragma unroll
    for (int q = 0; q < CH / 4; q++) {
        local[q * 4 + 0] = raw[q].x;
        local[q * 4 + 1] = raw[q].y;
        local[q * 4 + 2] = raw[q].z;
        local[q * 4 + 3] = raw[q].w;
    }
    int tot = 0;
#pragma unroll
    for (int j = 0; j < CH; j++) tot += local[j];
    int inc = tot;
#pragma unroll
    for (int o = 1; o < 32; o <<= 1) {
        int v = __shfl_up_sync(0xffffffff, inc, o);
        if (lane >= o) inc += v;
    }
    if (lane == 31) wsum[wid] = inc;
    __syncthreads();
    if (wid == 0) {
        int v = wsum[lane];
        int iv = v;
#pragma unroll
        for (int o = 1; o < 32; o <<= 1) {
            int u = __shfl_up_sync(0xffffffff, iv, o);
            if (lane >= o) iv += u;
        }
        wsum[lane] = iv - v;
    }
    __syncthreads();
    int run = wsum[wid] + (inc - tot);
    int base = tid * CH;
#pragma unroll
    for (int j = 0; j < CH; j++) {
        int idx = base + j;
        if (idx < NN) {
            d_off[idx] = run;
            d_cur[idx] = run;
        }
        run += local[j];
    }
}

__global__ void scatter_kernel(const int* __restrict__ ei, int E) {
    int e = (blockIdx.x * blockDim.x + threadIdx.x) * 4;
    if (e + 4 <= E) {
        int c0 = ei[E + e], c1 = ei[E + e + 1], c2 = ei[E + e + 2], c3 = ei[E + e + 3];
        int r0 = ei[e], r1 = ei[e + 1], r2 = ei[e + 2], r3 = ei[e + 3];
        int p0 = atomicAdd(&d_cur[c0], 1);
        int p1 = atomicAdd(&d_cur[c1], 1);
        int p2 = atomicAdd(&d_cur[c2], 1);
        int p3 = atomicAdd(&d_cur[c3], 1);
        d_rows[p0] = (unsigned short)r0;
        d_rows[p1] = (unsigned short)r1;
        d_rows[p2] = (unsigned short)r2;
        d_rows[p3] = (unsigned short)r3;
    } else {
        for (; e < E; e++) {
            int p = atomicAdd(&d_cur[ei[E + e]], 1);
            d_rows[p] = (unsigned short)ei[e];
        }
    }
}

// ---------------- aggregation: warp per node, fp16 gathers, fp32 accumulate ----------------
template<int LAYER>
__global__ void __launch_bounds__(256) agg_kernel() {
    const uint2* base = (LAYER == 0) ? d_xh : d_hh;
    int node = (blockIdx.x * blockDim.x + threadIdx.x) >> 5;
    int lane = threadIdx.x & 31;
    if (node >= NN) return;
    int start = d_off[node];
    int deg = d_hist[node];
    float ws = (LAYER == 0) ? 1.f : d_w[node];
    float4 a0 = make_float4(0.f, 0.f, 0.f, 0.f);
    float4 a1 = a0, a2 = a0, a3 = a0;
    f4fma(a0, h4tof4(base[node * 32 + lane]), ws);   // self
    int e = 0;
    for (; e + 4 <= deg; e += 4) {
        int i0 = d_rows[start + e + 0];
        int i1 = d_rows[start + e + 1];
        int i2 = d_rows[start + e + 2];
        int i3 = d_rows[start + e + 3];
        uint2 u0 = base[i0 * 32 + lane];
        uint2 u1 = base[i1 * 32 + lane];
        uint2 u2 = base[i2 * 32 + lane];
        uint2 u3 = base[i3 * 32 + lane];
        float w0 = (LAYER == 0) ? 1.f : d_w[i0];
        float w1 = (LAYER == 0) ? 1.f : d_w[i1];
        float w2 = (LAYER == 0) ? 1.f : d_w[i2];
        float w3 = (LAYER == 0) ? 1.f : d_w[i3];
        f4fma(a0, h4tof4(u0), w0);
        f4fma(a1, h4tof4(u1), w1);
        f4fma(a2, h4tof4(u2), w2);
        f4fma(a3, h4tof4(u3), w3);
    }
    for (; e < deg; e++) {
        int i0 = d_rows[start + e];
        float w0 = (LAYER == 0) ? 1.f : d_w[i0];
        f4fma(a0, h4tof4(base[i0 * 32 + lane]), w0);
    }
    f4acc(a0, a1);
    f4acc(a2, a3);
    f4acc(a0, a2);
    ((float4*)d_z)[node * 32 + lane] = a0;
}

// ---------------- fused MLP: y=z@W1+b1 -> BN stats (grid spin) -> relu(bn(y))@W2+b2 -> relu -> fp16 h, attn s ----
// __launch_bounds__(256,2): all 157 blocks co-resident => spin is safe.
__global__ void __launch_bounds__(256, 2)
mlp_kernel(const float* __restrict__ W1, const float* __restrict__ b1,
           const float* __restrict__ g, const float* __restrict__ be, float invn,
           const float* __restrict__ W2, const float* __restrict__ b2,
           const float* __restrict__ aw, const float* __restrict__ ab, int flagIdx) {
    __shared__ float As[64][HID];   // 32KB: A tile, then y' tile
    __shared__ float Bs[32][HID];   // 16KB: W chunks / reduction scratch
    int tid = threadIdx.x;
    int tx = tid & 15, ty = tid >> 4;
    int row0 = blockIdx.x * 64;

    // ---- load A tile (z) ----
#pragma unroll
    for (int l = 0; l < 8; l++) {
        int fid = tid + l * 256;
        int r = fid >> 5, c4 = fid & 31;
        float4 v = make_float4(0.f, 0.f, 0.f, 0.f);
        if (row0 + r < NN) v = *(const float4*)(d_z + (size_t)(row0 + r) * HID + c4 * 4);
        *(float4*)&As[r][c4 * 4] = v;
    }
    float acc[4][8];
    {
        float bj[8];
#pragma unroll
        for (int jj = 0; jj < 8; jj++) bj[jj] = b1[tx * 8 + jj];
#pragma unroll
        for (int ii = 0; ii < 4; ii++)
#pragma unroll
            for (int jj = 0; jj < 8; jj++) acc[ii][jj] = bj[jj];
    }

    // ---- mainloop 1: y = z @ W1 ----
#pragma unroll
    for (int kc = 0; kc < 4; kc++) {
        __syncthreads();
#pragma unroll
        for (int l = 0; l < 4; l++) {
            int fid = tid + l * 256;
            int r = fid >> 5, c4 = fid & 31;
            *(float4*)&Bs[r][c4 * 4] = *(const float4*)(W1 + (size_t)(kc * 32 + r) * HID + c4 * 4);
        }
        __syncthreads();
#pragma unroll 4
        for (int kk = 0; kk < 32; kk++) {
            int k = kc * 32 + kk;
            float aa[4];
#pragma unroll
            for (int ii = 0; ii < 4; ii++) aa[ii] = As[ty * 4 + ii][k];
            float4 b0 = *(const float4*)&Bs[kk][tx * 8];
            float4 b1v = *(const float4*)&Bs[kk][tx * 8 + 4];
            float bb[8] = {b0.x, b0.y, b0.z, b0.w, b1v.x, b1v.y, b1v.z, b1v.w};
#pragma unroll
            for (int ii = 0; ii < 4; ii++)
#pragma unroll
                for (int jj = 0; jj < 8; jj++) acc[ii][jj] += aa[ii] * bb[jj];
        }
    }

    // ---- BN stats ----
    {
        float p[8], q[8];
#pragma unroll
        for (int jj = 0; jj < 8; jj++) { p[jj] = 0.f; q[jj] = 0.f; }
#pragma unroll
        for (int ii = 0; ii < 4; ii++) {
            int r = row0 + ty * 4 + ii;
            if (r < NN) {
#pragma unroll
                for (int jj = 0; jj < 8; jj++) {
                    float v = acc[ii][jj];
                    p[jj] += v;
                    q[jj] += v * v;
                }
            }
        }
        float* red = &Bs[0][0];
        __syncthreads();
#pragma unroll
        for (int jj = 0; jj < 8; jj++) red[ty * HID + tx * 8 + jj] = p[jj];
        __syncthreads();
        if (tid < HID) {
            float sv = 0.f;
#pragma unroll
            for (int t = 0; t < 16; t++) sv += red[t * HID + tid];
            atomicAdd(&d_colsum[tid], sv);
        }
        __syncthreads();
#pragma unroll
        for (int jj = 0; jj < 8; jj++) red[ty * HID + tx * 8 + jj] = q[jj];
        __syncthreads();
        if (tid < HID) {
            float sv = 0.f;
#pragma unroll
            for (int t = 0; t < 16; t++) sv += red[t * HID + tid];
            atomicAdd(&d_colsum2[tid], sv);
        }
    }

    // ---- last block publishes scale/shift; everyone spins ----
    __threadfence();
    __syncthreads();
    if (tid == 0) {
        unsigned t = atomicInc(&d_ticket, gridDim.x - 1);   // wraps to 0 on last
        *(int*)&Bs[0][0] = (t == gridDim.x - 1);
    }
    __syncthreads();
    if (*(int*)&Bs[0][0]) {
        if (tid < HID) {
            float m = d_colsum[tid] * invn;
            float var = d_colsum2[tid] * invn - m * m;
            float rs = rsqrtf(var + BN_EPS);
            float sc = g[tid] * rs;
            d_scale[tid] = sc;
            d_shift[tid] = be[tid] - m * sc;
            d_colsum[tid] = 0.f;
            d_colsum2[tid] = 0.f;
        }
        __syncthreads();
        if (tid == 0) {
            __threadfence();
            atomicExch(&d_flag[flagIdx], 1);
        }
    }
    if (tid == 0) {
        while (atomicAdd(&d_flag[flagIdx], 0) == 0) __nanosleep(64);
    }
    __syncthreads();
    __threadfence();

    // ---- apply BN+relu, stage y' into As ----
    {
        float scj[8], shj[8];
#pragma unroll
        for (int jj = 0; jj < 8; jj++) {
            scj[jj] = d_scale[tx * 8 + jj];
            shj[jj] = d_shift[tx * 8 + jj];
        }
        __syncthreads();
#pragma unroll
        for (int ii = 0; ii < 4; ii++)
#pragma unroll
            for (int jj = 0; jj < 8; jj++)
                As[ty * 4 + ii][tx * 8 + jj] = fmaxf(acc[ii][jj] * scj[jj] + shj[jj], 0.f);
    }
    float awj[8];
    {
        float bj[8];
#pragma unroll
        for (int jj = 0; jj < 8; jj++) { bj[jj] = b2[tx * 8 + jj]; awj[jj] = aw[tx * 8 + jj]; }
#pragma unroll
        for (int ii = 0; ii < 4; ii++)
#pragma unroll
            for (int jj = 0; jj < 8; jj++) acc[ii][jj] = bj[jj];
    }

    // ---- mainloop 2: h = y' @ W2 ----
#pragma unroll
    for (int kc = 0; kc < 4; kc++) {
        __syncthreads();
#pragma unroll
        for (int l = 0; l < 4; l++) {
            int fid = tid + l * 256;
            int r = fid >> 5, c4 = fid & 31;
            *(float4*)&Bs[r][c4 * 4] = *(const float4*)(W2 + (size_t)(kc * 32 + r) * HID + c4 * 4);
        }
        __syncthreads();
#pragma unroll 4
        for (int kk = 0; kk < 32; kk++) {
            int k = kc * 32 + kk;
            float aa[4];
#pragma unroll
            for (int ii = 0; ii < 4; ii++) aa[ii] = As[ty * 4 + ii][k];
            float4 b0 = *(const float4*)&Bs[kk][tx * 8];
            float4 b1v = *(const float4*)&Bs[kk][tx * 8 + 4];
            float bb[8] = {b0.x, b0.y, b0.z, b0.w, b1v.x, b1v.y, b1v.z, b1v.w};
#pragma unroll
            for (int ii = 0; ii < 4; ii++)
#pragma unroll
                for (int jj = 0; jj < 8; jj++) acc[ii][jj] += aa[ii] * bb[jj];
        }
    }

    // ---- epilogue: relu -> fp16 store + attention score ----
    float sp[4] = {0.f, 0.f, 0.f, 0.f};
#pragma unroll
    for (int ii = 0; ii < 4; ii++) {
        int r = row0 + ty * 4 + ii;
        if (r < NN) {
            float v[8];
#pragma unroll
            for (int jj = 0; jj < 8; jj++) {
                v[jj] = fmaxf(acc[ii][jj], 0.f);
                sp[ii] += v[jj] * awj[jj];
            }
            uint2 u0, u1;
            *(__half2*)&u0.x = __floats2half2_rn(v[0], v[1]);
            *(__half2*)&u0.y = __floats2half2_rn(v[2], v[3]);
            *(__half2*)&u1.x = __floats2half2_rn(v[4], v[5]);
            *(__half2*)&u1.y = __floats2half2_rn(v[6], v[7]);
            d_hh[r * 32 + tx * 2 + 0] = u0;
            d_hh[r * 32 + tx * 2 + 1] = u1;
        }
    }
    float* red = &Bs[0][0];   // 64*16 floats
    __syncthreads();
#pragma unroll
    for (int ii = 0; ii < 4; ii++) red[(ty * 4 + ii) * 16 + tx] = sp[ii];
    __syncthreads();
    if (tid < 64) {
        float v = 0.f;
#pragma unroll
        for (int t = 0; t < 16; t++) v += red[tid * 16 + t];
        int r = row0 + tid;
        if (r < NN) d_s[r] = 1.f / (1.f + expf(-(v + ab[0])));
    }
}

// ---------------- tst: w[i] = s[i] * sum_{j in CSR[i]} s[j]  (warp per node) ----------------
__global__ void __launch_bounds__(256) tst_kernel() {
    int node = (blockIdx.x * blockDim.x + threadIdx.x) >> 5;
    int lane = threadIdx.x & 31;
    if (node >= NN) return;
    int start = d_off[node];
    int deg = d_hist[node];
    float t = 0.f;
    for (int e = lane; e < deg; e += 32) t += d_s[d_rows[start + e]];
#pragma unroll
    for (int o = 16; o; o >>= 1) t += __shfl_xor_sync(0xffffffff, t, o);
    if (lane == 0) d_w[node] = d_s[node] * t;
}

// ---------------- pool: hg[batch[i]] += h[i]*w[i]  (warp per node, w inline) ----------------
__global__ void __launch_bounds__(256) tstpool_kernel(const int* __restrict__ batch) {
    int node = (blockIdx.x * blockDim.x + threadIdx.x) >> 5;
    int lane = threadIdx.x & 31;
    if (node >= NN) return;
    int start = d_off[node];
    int deg = d_hist[node];
    float t = 0.f;
    for (int e = lane; e < deg; e += 32) t += d_s[d_rows[start + e]];
#pragma unroll
    for (int o = 16; o; o >>= 1) t += __shfl_xor_sync(0xffffffff, t, o);
    float w = d_s[node] * t;
    float4 hv = h4tof4(d_hh[node * 32 + lane]);
    int b = batch[node];
    float* dst = &d_hg[b * HID + lane * 4];
    atomicAdd(dst + 0, hv.x * w);
    atomicAdd(dst + 1, hv.y * w);
    atomicAdd(dst + 2, hv.z * w);
    atomicAdd(dst + 3, hv.w * w);
}

// ---------------- head: MLP(hg) + log_softmax, single block ----------------
__global__ void __launch_bounds__(256)
head_kernel(const float* __restrict__ w1, const float* __restrict__ b1,
            const float* __restrict__ g, const float* __restrict__ be,
            const float* __restrict__ w2, const float* __restrict__ b2,
            float* __restrict__ out) {
    __shared__ float ys[GG][HID];
    __shared__ float sc[HID], sh[HID];
    __shared__ float logits[GG * OUTC];
    int tid = threadIdx.x;

#pragma unroll
    for (int l = 0; l < 8; l++) {
        int idx = tid + l * 256;
        ((float4*)&ys[0][0])[idx] = ((const float4*)d_hg)[idx];
    }
    __syncthreads();

    int row = tid >> 2;
    int c0 = (tid & 3) * 32;
    float acc[32];
#pragma unroll
    for (int j = 0; j < 32; j++) acc[j] = b1[c0 + j];
    for (int k = 0; k < HID; k++) {
        float a = ys[row][k];
#pragma unroll
        for (int j4 = 0; j4 < 8; j4++) {
            float4 w = *(const float4*)(w1 + (size_t)k * HID + c0 + j4 * 4);
            acc[j4 * 4 + 0] += a * w.x;
            acc[j4 * 4 + 1] += a * w.y;
            acc[j4 * 4 + 2] += a * w.z;
            acc[j4 * 4 + 3] += a * w.w;
        }
    }
    __syncthreads();
#pragma unroll
    for (int j = 0; j < 32; j++) ys[row][c0 + j] = acc[j];
    __syncthreads();

    if (tid < HID) {
        float s1 = 0.f, s2 = 0.f;
#pragma unroll 8
        for (int r = 0; r < GG; r++) {
            float v = ys[r][tid];
            s1 += v;
            s2 += v * v;
        }
        float m = s1 / GG;
        float var = s2 / GG - m * m;
        float rs = rsqrtf(var + BN_EPS);
        float scale = g[tid] * rs;
        sc[tid] = scale;
        sh[tid] = be[tid] - m * scale;
    }
    __syncthreads();

    for (int idx = tid; idx < GG * OUTC; idx += 256) {
        int gr = idx / OUTC, o = idx - gr * OUTC;
        float v = b2[o];
        for (int k = 0; k < HID; k++) {
            float hv = fmaxf(ys[gr][k] * sc[k] + sh[k], 0.f);
            v += hv * w2[k * OUTC + o];
        }
        logits[idx] = v;
    }
    __syncthreads();

    if (tid < GG) {
        float mx = -1e30f;
#pragma unroll
        for (int o = 0; o < OUTC; o++) mx = fmaxf(mx, logits[tid * OUTC + o]);
        float sum = 0.f;
#pragma unroll
        for (int o = 0; o < OUTC; o++) sum += expf(logits[tid * OUTC + o] - mx);
        float ls = mx + logf(sum);
#pragma unroll
        for (int o = 0; o < OUTC; o++) out[tid * OUTC + o] = logits[tid * OUTC + o] - ls;
    }
}

// ---------------- host launch ----------------
extern "C" void kernel_launch(void* const* d_in, const int* in_sizes, int n_in,
                              void* d_out, int out_size) {
    const float* x = (const float*)d_in[0];
    const int* ei = (const int*)d_in[1];
    const int* batch = (const int*)d_in[2];
    const float* c1_w1 = (const float*)d_in[3];
    const float* c1_b1 = (const float*)d_in[4];
    const float* c1_g  = (const float*)d_in[5];
    const float* c1_be = (const float*)d_in[6];
    const float* c1_w2 = (const float*)d_in[7];
    const float* c1_b2 = (const float*)d_in[8];
    const float* a1_w  = (const float*)d_in[9];
    const float* a1_b  = (const float*)d_in[10];
    const float* c2_w1 = (const float*)d_in[11];
    const float* c2_b1 = (const float*)d_in[12];
    const float* c2_g  = (const float*)d_in[13];
    const float* c2_be = (const float*)d_in[14];
    const float* c2_w2 = (const float*)d_in[15];
    const float* c2_b2 = (const float*)d_in[16];
    const float* a2_w  = (const float*)d_in[17];
    const float* a2_b  = (const float*)d_in[18];
    const float* l_w1  = (const float*)d_in[19];
    const float* l_b1  = (const float*)d_in[20];
    const float* l_g   = (const float*)d_in[21];
    const float* l_be  = (const float*)d_in[22];
    const float* l_w2  = (const float*)d_in[23];
    const float* l_b2  = (const float*)d_in[24];
    float* out = (float*)d_out;

    int E = in_sizes[1] / 2;

    const int GEMM_GRID = (NN + 63) / 64;        // 157
    const int WARP_GRID = (NN * 32 + 255) / 256; // 1250 (warp per node)
    const int E4_GRID = ((E + 3) / 4 + 255) / 256;

    // init + CSR build
    init_kernel<<<(NN * HID / 2 + 255) / 256, 256>>>(x);
    hist_kernel<<<E4_GRID, 256>>>(ei, E);
    scan_kernel<<<1, 1024>>>();
    scatter_kernel<<<E4_GRID, 256>>>(ei, E);

    // GIN layer 1 (fused MLP)
    agg_kernel<0><<<WARP_GRID, 256>>>();
    mlp_kernel<<<GEMM_GRID, 256>>>(c1_w1, c1_b1, c1_g, c1_be, 1.f / NN,
                                   c1_w2, c1_b2, a1_w, a1_b, 0);
    tst_kernel<<<WARP_GRID, 256>>>();

    // GIN layer 2
    agg_kernel<1><<<WARP_GRID, 256>>>();
    mlp_kernel<<<GEMM_GRID, 256>>>(c2_w1, c2_b1, c2_g, c2_be, 1.f / NN,
                                   c2_w2, c2_b2, a2_w, a2_b, 1);
    tstpool_kernel<<<WARP_GRID, 256>>>(batch);

    // head
    head_kernel<<<1, 256>>>(l_w1, l_b1, l_g, l_be, l_w2, l_b2, out);
}

// round 15
// speedup vs baseline: 1.1364x; 1.0143x over previous
#include <cuda_runtime.h>
#include <cuda_fp16.h>

#define NN 10000
#define GG 64
#define HID 128
#define OUTC 10
#define BN_EPS 1e-5f
#define EE_MAX 640000
#define NH 16384   // padded histogram length (entries >= NN stay zero forever)

// ---------------- scratch (device globals) ----------------
__device__ int   d_hist[NH];            // zero at entry (module-load init, then scan self-resets)
__device__ int   d_off[NN + 1];         // exclusive prefix + sentinel E
__device__ int   d_cur[NN];
__device__ int   d_rows[EE_MAX];
__device__ uint2 d_xh[NN * HID / 4];    // x as fp16 (4 halves per uint2)
__device__ uint2 d_hh[NN * HID / 4];    // h (post-GIN relu) as fp16
__device__ float d_z[NN * HID];
__device__ float d_s[NN];
__device__ float d_w[NN];               // s[i] * sum_{j in CSR[i]} s[j]
__device__ float d_colsum[HID];
__device__ float d_colsum2[HID];
__device__ float d_scale[HID];
__device__ float d_shift[HID];
__device__ float d_hg[GG * HID];
__device__ unsigned d_ticket;           // zero-init; atomicInc wraps (graph-replay safe)
__device__ int   d_flag[2];             // per-layer BN-ready flag (reset each call)

__device__ __forceinline__ void f4acc(float4& a, const float4 v) {
    a.x += v.x; a.y += v.y; a.z += v.z; a.w += v.w;
}
__device__ __forceinline__ void f4fma(float4& a, const float4 v, float s) {
    a.x += v.x * s; a.y += v.y * s; a.z += v.z * s; a.w += v.w * s;
}
__device__ __forceinline__ float4 h4tof4(const uint2 u) {
    float2 f01 = __half22float2(*(const __half2*)&u.x);
    float2 f23 = __half22float2(*(const __half2*)&u.y);
    return make_float4(f01.x, f01.y, f23.x, f23.y);
}

// ---------------- init + hist fused: zero scratch, cvt x->fp16, histogram cols ----------------
// d_hist is zero at entry (scan_kernel resets it after consuming).
__global__ void init_hist_kernel(const float* __restrict__ x, const int* __restrict__ ei, int E) {
    int i = blockIdx.x * blockDim.x + threadIdx.x;
    if (i < NN * HID / 2) {
        float2 f = ((const float2*)x)[i];
        ((__half2*)d_xh)[i] = __floats2half2_rn(f.x, f.y);
    }
    if (i < HID) { d_colsum[i] = 0.f; d_colsum2[i] = 0.f; }
    if (i < GG * HID) d_hg[i] = 0.f;
    if (i < 2) d_flag[i] = 0;
    int e = i * 4;
    if (e + 4 <= E) {
        int c0 = ei[E + e], c1 = ei[E + e + 1], c2 = ei[E + e + 2], c3 = ei[E + e + 3];
        atomicAdd(&d_hist[c0], 1);
        atomicAdd(&d_hist[c1], 1);
        atomicAdd(&d_hist[c2], 1);
        atomicAdd(&d_hist[c3], 1);
    } else {
        for (; e < E; e++) atomicAdd(&d_hist[ei[E + e]], 1);
    }
}

// single-block scan, warp-shuffle based; consumes AND re-zeroes d_hist; writes sentinel d_off[NN]
__global__ void scan_kernel() {
    __shared__ int wsum[32];
    const int CH = NH / 1024;  // 16
    int tid = threadIdx.x;
    int lane = tid & 31, wid = tid >> 5;
    int local[CH];
    int4 raw[CH / 4];
#pragma unroll
    for (int q = 0; q < CH / 4; q++) raw[q] = ((const int4*)d_hist)[tid * (CH / 4) + q];
    // reset for next call (consume-and-reset keeps entry invariant: d_hist == 0)
    int4 z4 = make_int4(0, 0, 0, 0);
#pragma unroll
    for (int q = 0; q < CH / 4; q++) ((int4*)d_hist)[tid * (CH / 4) + q] = z4;
#pragma unroll
    for (int q = 0; q < CH / 4; q++) {
        local[q * 4 + 0] = raw[q].x;
        local[q * 4 + 1] = raw[q].y;
        local[q * 4 + 2] = raw[q].z;
        local[q * 4 + 3] = raw[q].w;
    }
    int tot = 0;
#pragma unroll
    for (int j = 0; j < CH; j++) tot += local[j];
    int inc = tot;
#pragma unroll
    for (int o = 1; o < 32; o <<= 1) {
        int v = __shfl_up_sync(0xffffffff, inc, o);
        if (lane >= o) inc += v;
    }
    if (lane == 31) wsum[wid] = inc;
    __syncthreads();
    if (wid == 0) {
        int v = wsum[lane];
        int iv = v;
#pragma unroll
        for (int o = 1; o < 32; o <<= 1) {
            int u = __shfl_up_sync(0xffffffff, iv, o);
            if (lane >= o) iv += u;
        }
        wsum[lane] = iv - v;
    }
    __syncthreads();
    int run = wsum[wid] + (inc - tot);
    int base = tid * CH;
#pragma unroll
    for (int j = 0; j < CH; j++) {
        int idx = base + j;
        if (idx < NN) {
            d_off[idx] = run;
            d_cur[idx] = run;
        }
        run += local[j];
    }
    if (tid == 1023) d_off[NN] = run;   // == E (padded entries are zero)
}

__global__ void scatter_kernel(const int* __restrict__ ei, int E) {
    int e = (blockIdx.x * blockDim.x + threadIdx.x) * 4;
    if (e + 4 <= E) {
        int c0 = ei[E + e], c1 = ei[E + e + 1], c2 = ei[E + e + 2], c3 = ei[E + e + 3];
        int r0 = ei[e], r1 = ei[e + 1], r2 = ei[e + 2], r3 = ei[e + 3];
        int p0 = atomicAdd(&d_cur[c0], 1);
        int p1 = atomicAdd(&d_cur[c1], 1);
        int p2 = atomicAdd(&d_cur[c2], 1);
        int p3 = atomicAdd(&d_cur[c3], 1);
        d_rows[p0] = r0;
        d_rows[p1] = r1;
        d_rows[p2] = r2;
        d_rows[p3] = r3;
    } else {
        for (; e < E; e++) {
            int p = atomicAdd(&d_cur[ei[E + e]], 1);
            d_rows[p] = ei[e];
        }
    }
}

// ---------------- aggregation: warp per node, fp16 gathers, fp32 accumulate, MLP=8 ----------------
template<int LAYER>
__global__ void __launch_bounds__(256) agg_kernel() {
    const uint2* base = (LAYER == 0) ? d_xh : d_hh;
    int node = (blockIdx.x * blockDim.x + threadIdx.x) >> 5;
    int lane = threadIdx.x & 31;
    if (node >= NN) return;
    int start = d_off[node];
    int deg = d_off[node + 1] - start;
    float ws = (LAYER == 0) ? 1.f : d_w[node];
    float4 a0 = make_float4(0.f, 0.f, 0.f, 0.f);
    float4 a1 = a0, a2 = a0, a3 = a0;
    f4fma(a0, h4tof4(base[node * 32 + lane]), ws);   // self
    int e = 0;
    for (; e + 8 <= deg; e += 8) {
        int idx[8];
#pragma unroll
        for (int q = 0; q < 8; q++) idx[q] = d_rows[start + e + q];
        uint2 u[8];
#pragma unroll
        for (int q = 0; q < 8; q++) u[q] = base[idx[q] * 32 + lane];
        float w[8];
#pragma unroll
        for (int q = 0; q < 8; q++) w[q] = (LAYER == 0) ? 1.f : d_w[idx[q]];
        f4fma(a0, h4tof4(u[0]), w[0]);
        f4fma(a1, h4tof4(u[1]), w[1]);
        f4fma(a2, h4tof4(u[2]), w[2]);
        f4fma(a3, h4tof4(u[3]), w[3]);
        f4fma(a0, h4tof4(u[4]), w[4]);
        f4fma(a1, h4tof4(u[5]), w[5]);
        f4fma(a2, h4tof4(u[6]), w[6]);
        f4fma(a3, h4tof4(u[7]), w[7]);
    }
    for (; e + 4 <= deg; e += 4) {
        int i0 = d_rows[start + e + 0];
        int i1 = d_rows[start + e + 1];
        int i2 = d_rows[start + e + 2];
        int i3 = d_rows[start + e + 3];
        uint2 u0 = base[i0 * 32 + lane];
        uint2 u1 = base[i1 * 32 + lane];
        uint2 u2 = base[i2 * 32 + lane];
        uint2 u3 = base[i3 * 32 + lane];
        float w0 = (LAYER == 0) ? 1.f : d_w[i0];
        float w1 = (LAYER == 0) ? 1.f : d_w[i1];
        float w2 = (LAYER == 0) ? 1.f : d_w[i2];
        float w3 = (LAYER == 0) ? 1.f : d_w[i3];
        f4fma(a0, h4tof4(u0), w0);
        f4fma(a1, h4tof4(u1), w1);
        f4fma(a2, h4tof4(u2), w2);
        f4fma(a3, h4tof4(u3), w3);
    }
    for (; e < deg; e++) {
        int i0 = d_rows[start + e];
        float w0 = (LAYER == 0) ? 1.f : d_w[i0];
        f4fma(a0, h4tof4(base[i0 * 32 + lane]), w0);
    }
    f4acc(a0, a1);
    f4acc(a2, a3);
    f4acc(a0, a2);
    ((float4*)d_z)[node * 32 + lane] = a0;
}

// ---------------- fused MLP: y=z@W1+b1 -> BN stats (grid spin) -> relu(bn(y))@W2+b2 -> relu -> fp16 h, attn s ----
// __launch_bounds__(256,2): all 157 blocks co-resident => spin is safe.
__global__ void __launch_bounds__(256, 2)
mlp_kernel(const float* __restrict__ W1, const float* __restrict__ b1,
           const float* __restrict__ g, const float* __restrict__ be, float invn,
           const float* __restrict__ W2, const float* __restrict__ b2,
           const float* __restrict__ aw, const float* __restrict__ ab, int flagIdx) {
    __shared__ float As[64][HID];   // 32KB: A tile, then y' tile
    __shared__ float Bs[32][HID];   // 16KB: W chunks / reduction scratch
    int tid = threadIdx.x;
    int tx = tid & 15, ty = tid >> 4;
    int row0 = blockIdx.x * 64;

#pragma unroll
    for (int l = 0; l < 8; l++) {
        int fid = tid + l * 256;
        int r = fid >> 5, c4 = fid & 31;
        float4 v = make_float4(0.f, 0.f, 0.f, 0.f);
        if (row0 + r < NN) v = *(const float4*)(d_z + (size_t)(row0 + r) * HID + c4 * 4);
        *(float4*)&As[r][c4 * 4] = v;
    }
    float acc[4][8];
    {
        float bj[8];
#pragma unroll
        for (int jj = 0; jj < 8; jj++) bj[jj] = b1[tx * 8 + jj];
#pragma unroll
        for (int ii = 0; ii < 4; ii++)
#pragma unroll
            for (int jj = 0; jj < 8; jj++) acc[ii][jj] = bj[jj];
    }

#pragma unroll
    for (int kc = 0; kc < 4; kc++) {
        __syncthreads();
#pragma unroll
        for (int l = 0; l < 4; l++) {
            int fid = tid + l * 256;
            int r = fid >> 5, c4 = fid & 31;
            *(float4*)&Bs[r][c4 * 4] = *(const float4*)(W1 + (size_t)(kc * 32 + r) * HID + c4 * 4);
        }
        __syncthreads();
#pragma unroll 4
        for (int kk = 0; kk < 32; kk++) {
            int k = kc * 32 + kk;
            float aa[4];
#pragma unroll
            for (int ii = 0; ii < 4; ii++) aa[ii] = As[ty * 4 + ii][k];
            float4 b0 = *(const float4*)&Bs[kk][tx * 8];
            float4 b1v = *(const float4*)&Bs[kk][tx * 8 + 4];
            float bb[8] = {b0.x, b0.y, b0.z, b0.w, b1v.x, b1v.y, b1v.z, b1v.w};
#pragma unroll
            for (int ii = 0; ii < 4; ii++)
#pragma unroll
                for (int jj = 0; jj < 8; jj++) acc[ii][jj] += aa[ii] * bb[jj];
        }
    }

    // ---- BN stats ----
    {
        float p[8], q[8];
#pragma unroll
        for (int jj = 0; jj < 8; jj++) { p[jj] = 0.f; q[jj] = 0.f; }
#pragma unroll
        for (int ii = 0; ii < 4; ii++) {
            int r = row0 + ty * 4 + ii;
            if (r < NN) {
#pragma unroll
                for (int jj = 0; jj < 8; jj++) {
                    float v = acc[ii][jj];
                    p[jj] += v;
                    q[jj] += v * v;
                }
            }
        }
        float* red = &Bs[0][0];
        __syncthreads();
#pragma unroll
        for (int jj = 0; jj < 8; jj++) red[ty * HID + tx * 8 + jj] = p[jj];
        __syncthreads();
        if (tid < HID) {
            float sv = 0.f;
#pragma unroll
            for (int t = 0; t < 16; t++) sv += red[t * HID + tid];
            atomicAdd(&d_colsum[tid], sv);
        }
        __syncthreads();
#pragma unroll
        for (int jj = 0; jj < 8; jj++) red[ty * HID + tx * 8 + jj] = q[jj];
        __syncthreads();
        if (tid < HID) {
            float sv = 0.f;
#pragma unroll
            for (int t = 0; t < 16; t++) sv += red[t * HID + tid];
            atomicAdd(&d_colsum2[tid], sv);
        }
    }

    // ---- last block publishes scale/shift; everyone spins ----
    __threadfence();
    __syncthreads();
    if (tid == 0) {
        unsigned t = atomicInc(&d_ticket, gridDim.x - 1);
        *(int*)&Bs[0][0] = (t == gridDim.x - 1);
    }
    __syncthreads();
    if (*(int*)&Bs[0][0]) {
        if (tid < HID) {
            float m = d_colsum[tid] * invn;
            float var = d_colsum2[tid] * invn - m * m;
            float rs = rsqrtf(var + BN_EPS);
            float sc = g[tid] * rs;
            d_scale[tid] = sc;
            d_shift[tid] = be[tid] - m * sc;
            d_colsum[tid] = 0.f;
            d_colsum2[tid] = 0.f;
        }
        __syncthreads();
        if (tid == 0) {
            __threadfence();
            atomicExch(&d_flag[flagIdx], 1);
        }
    }
    if (tid == 0) {
        while (atomicAdd(&d_flag[flagIdx], 0) == 0) __nanosleep(64);
    }
    __syncthreads();
    __threadfence();

    // ---- apply BN+relu, stage y' into As ----
    {
        float scj[8], shj[8];
#pragma unroll
        for (int jj = 0; jj < 8; jj++) {
            scj[jj] = d_scale[tx * 8 + jj];
            shj[jj] = d_shift[tx * 8 + jj];
        }
        __syncthreads();
#pragma unroll
        for (int ii = 0; ii < 4; ii++)
#pragma unroll
            for (int jj = 0; jj < 8; jj++)
                As[ty * 4 + ii][tx * 8 + jj] = fmaxf(acc[ii][jj] * scj[jj] + shj[jj], 0.f);
    }
    float awj[8];
    {
        float bj[8];
#pragma unroll
        for (int jj = 0; jj < 8; jj++) { bj[jj] = b2[tx * 8 + jj]; awj[jj] = aw[tx * 8 + jj]; }
#pragma unroll
        for (int ii = 0; ii < 4; ii++)
#pragma unroll
            for (int jj = 0; jj < 8; jj++) acc[ii][jj] = bj[jj];
    }

#pragma unroll
    for (int kc = 0; kc < 4; kc++) {
        __syncthreads();
#pragma unroll
        for (int l = 0; l < 4; l++) {
            int fid = tid + l * 256;
            int r = fid >> 5, c4 = fid & 31;
            *(float4*)&Bs[r][c4 * 4] = *(const float4*)(W2 + (size_t)(kc * 32 + r) * HID + c4 * 4);
        }
        __syncthreads();
#pragma unroll 4
        for (int kk = 0; kk < 32; kk++) {
            int k = kc * 32 + kk;
            float aa[4];
#pragma unroll
            for (int ii = 0; ii < 4; ii++) aa[ii] = As[ty * 4 + ii][k];
            float4 b0 = *(const float4*)&Bs[kk][tx * 8];
            float4 b1v = *(const float4*)&Bs[kk][tx * 8 + 4];
            float bb[8] = {b0.x, b0.y, b0.z, b0.w, b1v.x, b1v.y, b1v.z, b1v.w};
#pragma unroll
            for (int ii = 0; ii < 4; ii++)
#pragma unroll
                for (int jj = 0; jj < 8; jj++) acc[ii][jj] += aa[ii] * bb[jj];
        }
    }

    // ---- epilogue: relu -> fp16 store + attention score ----
    float sp[4] = {0.f, 0.f, 0.f, 0.f};
#pragma unroll
    for (int ii = 0; ii < 4; ii++) {
        int r = row0 + ty * 4 + ii;
        if (r < NN) {
            float v[8];
#pragma unroll
            for (int jj = 0; jj < 8; jj++) {
                v[jj] = fmaxf(acc[ii][jj], 0.f);
                sp[ii] += v[jj] * awj[jj];
            }
            uint2 u0, u1;
            *(__half2*)&u0.x = __floats2half2_rn(v[0], v[1]);
            *(__half2*)&u0.y = __floats2half2_rn(v[2], v[3]);
            *(__half2*)&u1.x = __floats2half2_rn(v[4], v[5]);
            *(__half2*)&u1.y = __floats2half2_rn(v[6], v[7]);
            d_hh[r * 32 + tx * 2 + 0] = u0;
            d_hh[r * 32 + tx * 2 + 1] = u1;
        }
    }
    float* red = &Bs[0][0];
    __syncthreads();
#pragma unroll
    for (int ii = 0; ii < 4; ii++) red[(ty * 4 + ii) * 16 + tx] = sp[ii];
    __syncthreads();
    if (tid < 64) {
        float v = 0.f;
#pragma unroll
        for (int t = 0; t < 16; t++) v += red[tid * 16 + t];
        int r = row0 + tid;
        if (r < NN) d_s[r] = 1.f / (1.f + expf(-(v + ab[0])));
    }
}

// ---------------- tst: w[i] = s[i] * sum_{j in CSR[i]} s[j]  (warp per node) ----------------
__global__ void __launch_bounds__(256) tst_kernel() {
    int node = (blockIdx.x * blockDim.x + threadIdx.x) >> 5;
    int lane = threadIdx.x & 31;
    if (node >= NN) return;
    int start = d_off[node];
    int deg = d_off[node + 1] - start;
    float t = 0.f;
    for (int e = lane; e < deg; e += 32) t += d_s[d_rows[start + e]];
#pragma unroll
    for (int o = 16; o; o >>= 1) t += __shfl_xor_sync(0xffffffff, t, o);
    if (lane == 0) d_w[node] = d_s[node] * t;
}

// ---------------- pool: hg[batch[i]] += h[i]*w[i]  (warp per node, w inline) ----------------
__global__ void __launch_bounds__(256) tstpool_kernel(const int* __restrict__ batch) {
    int node = (blockIdx.x * blockDim.x + threadIdx.x) >> 5;
    int lane = threadIdx.x & 31;
    if (node >= NN) return;
    int start = d_off[node];
    int deg = d_off[node + 1] - start;
    float t = 0.f;
    for (int e = lane; e < deg; e += 32) t += d_s[d_rows[start + e]];
#pragma unroll
    for (int o = 16; o; o >>= 1) t += __shfl_xor_sync(0xffffffff, t, o);
    float w = d_s[node] * t;
    float4 hv = h4tof4(d_hh[node * 32 + lane]);
    int b = batch[node];
    float* dst = &d_hg[b * HID + lane * 4];
    atomicAdd(dst + 0, hv.x * w);
    atomicAdd(dst + 1, hv.y * w);
    atomicAdd(dst + 2, hv.z * w);
    atomicAdd(dst + 3, hv.w * w);
}

// ---------------- head: MLP(hg) + log_softmax, single block ----------------
__global__ void __launch_bounds__(256)
head_kernel(const float* __restrict__ w1, const float* __restrict__ b1,
            const float* __restrict__ g, const float* __restrict__ be,
            const float* __restrict__ w2, const float* __restrict__ b2,
            float* __restrict__ out) {
    __shared__ float ys[GG][HID];
    __shared__ float sc[HID], sh[HID];
    __shared__ float logits[GG * OUTC];
    int tid = threadIdx.x;

#pragma unroll
    for (int l = 0; l < 8; l++) {
        int idx = tid + l * 256;
        ((float4*)&ys[0][0])[idx] = ((const float4*)d_hg)[idx];
    }
    __syncthreads();

    int row = tid >> 2;
    int c0 = (tid & 3) * 32;
    float acc[32];
#pragma unroll
    for (int j = 0; j < 32; j++) acc[j] = b1[c0 + j];
    for (int k = 0; k < HID; k++) {
        float a = ys[row][k];
#pragma unroll
        for (int j4 = 0; j4 < 8; j4++) {
            float4 w = *(const float4*)(w1 + (size_t)k * HID + c0 + j4 * 4);
            acc[j4 * 4 + 0] += a * w.x;
            acc[j4 * 4 + 1] += a * w.y;
            acc[j4 * 4 + 2] += a * w.z;
            acc[j4 * 4 + 3] += a * w.w;
        }
    }
    __syncthreads();
#pragma unroll
    for (int j = 0; j < 32; j++) ys[row][c0 + j] = acc[j];
    __syncthreads();

    if (tid < HID) {
        float s1 = 0.f, s2 = 0.f;
#pragma unroll 8
        for (int r = 0; r < GG; r++) {
            float v = ys[r][tid];
            s1 += v;
            s2 += v * v;
        }
        float m = s1 / GG;
        float var = s2 / GG - m * m;
        float rs = rsqrtf(var + BN_EPS);
        float scale = g[tid] * rs;
        sc[tid] = scale;
        sh[tid] = be[tid] - m * scale;
    }
    __syncthreads();

    for (int idx = tid; idx < GG * OUTC; idx += 256) {
        int gr = idx / OUTC, o = idx - gr * OUTC;
        float v = b2[o];
        for (int k = 0; k < HID; k++) {
            float hv = fmaxf(ys[gr][k] * sc[k] + sh[k], 0.f);
            v += hv * w2[k * OUTC + o];
        }
        logits[idx] = v;
    }
    __syncthreads();

    if (tid < GG) {
        float mx = -1e30f;
#pragma unroll
        for (int o = 0; o < OUTC; o++) mx = fmaxf(mx, logits[tid * OUTC + o]);
        float sum = 0.f;
#pragma unroll
        for (int o = 0; o < OUTC; o++) sum += expf(logits[tid * OUTC + o] - mx);
        float ls = mx + logf(sum);
#pragma unroll
        for (int o = 0; o < OUTC; o++) out[tid * OUTC + o] = logits[tid * OUTC + o] - ls;
    }
}

// ---------------- host launch ----------------
extern "C" void kernel_launch(void* const* d_in, const int* in_sizes, int n_in,
                              void* d_out, int out_size) {
    const float* x = (const float*)d_in[0];
    const int* ei = (const int*)d_in[1];
    const int* batch = (const int*)d_in[2];
    const float* c1_w1 = (const float*)d_in[3];
    const float* c1_b1 = (const float*)d_in[4];
    const float* c1_g  = (const float*)d_in[5];
    const float* c1_be = (const float*)d_in[6];
    const float* c1_w2 = (const float*)d_in[7];
    const float* c1_b2 = (const float*)d_in[8];
    const float* a1_w  = (const float*)d_in[9];
    const float* a1_b  = (const float*)d_in[10];
    const float* c2_w1 = (const float*)d_in[11];
    const float* c2_b1 = (const float*)d_in[12];
    const float* c2_g  = (const float*)d_in[13];
    const float* c2_be = (const float*)d_in[14];
    const float* c2_w2 = (const float*)d_in[15];
    const float* c2_b2 = (const float*)d_in[16];
    const float* a2_w  = (const float*)d_in[17];
    const float* a2_b  = (const float*)d_in[18];
    const float* l_w1  = (const float*)d_in[19];
    const float* l_b1  = (const float*)d_in[20];
    const float* l_g   = (const float*)d_in[21];
    const float* l_be  = (const float*)d_in[22];
    const float* l_w2  = (const float*)d_in[23];
    const float* l_b2  = (const float*)d_in[24];
    float* out = (float*)d_out;

    int E = in_sizes[1] / 2;

    const int GEMM_GRID = (NN + 63) / 64;        // 157
    const int WARP_GRID = (NN * 32 + 255) / 256; // 1250 (warp per node)
    const int E4_GRID = ((E + 3) / 4 + 255) / 256;

    // init (+hist fused) + CSR build
    init_hist_kernel<<<(NN * HID / 2 + 255) / 256, 256>>>(x, ei, E);
    scan_kernel<<<1, 1024>>>();
    scatter_kernel<<<E4_GRID, 256>>>(ei, E);

    // GIN layer 1 (fused MLP)
    agg_kernel<0><<<WARP_GRID, 256>>>();
    mlp_kernel<<<GEMM_GRID, 256>>>(c1_w1, c1_b1, c1_g, c1_be, 1.f / NN,
                                   c1_w2, c1_b2, a1_w, a1_b, 0);
    tst_kernel<<<WARP_GRID, 256>>>();

    // GIN layer 2
    agg_kernel<1><<<WARP_GRID, 256>>>();
    mlp_kernel<<<GEMM_GRID, 256>>>(c2_w1, c2_b1, c2_g, c2_be, 1.f / NN,
                                   c2_w2, c2_b2, a2_w, a2_b, 1);
    tstpool_kernel<<<WARP_GRID, 256>>>(batch);

    // head
    head_kernel<<<1, 256>>>(l_w1, l_b1, l_g, l_be, l_w2, l_b2, out);
}

// round 16
// speedup vs baseline: 1.1790x; 1.0374x over previous
#include <cuda_runtime.h>
#include <cuda_fp16.h>

#define NN 10000
#define GG 64
#define HID 128
#define OUTC 10
#define BN_EPS 1e-5f
#define EE_MAX 640000
#define NH 16384   // padded histogram length (entries >= NN stay zero forever)

// ---------------- scratch (device globals) ----------------
__device__ int   d_hist[NH];            // zero at entry (module-load init, then scan self-resets)
__device__ int   d_off[NN + 1];         // exclusive prefix + sentinel E
__device__ int   d_cur[NN];
__device__ int   d_rows[EE_MAX];
__device__ uint4 d_xh[NN * HID / 8];    // x as fp16 (8 halves per uint4, 16B-aligned rows)
__device__ uint4 d_hh[NN * HID / 8];    // h (post-GIN relu) as fp16
__device__ float d_z[NN * HID];
__device__ float d_s[NN];
__device__ float d_w[NN];               // s[i] * sum_{j in CSR[i]} s[j]
__device__ float d_colsum[HID];
__device__ float d_colsum2[HID];
__device__ float d_scale[HID];
__device__ float d_shift[HID];
__device__ float d_hg[GG * HID];
__device__ unsigned d_ticket;           // zero-init; atomicInc wraps (graph-replay safe)
__device__ int   d_flag[2];             // per-layer BN-ready flag (reset each call)

__device__ __forceinline__ void f4acc(float4& a, const float4 v) {
    a.x += v.x; a.y += v.y; a.z += v.z; a.w += v.w;
}
__device__ __forceinline__ float4 h4tof4(const uint2 u) {
    float2 f01 = __half22float2(*(const __half2*)&u.x);
    float2 f23 = __half22float2(*(const __half2*)&u.y);
    return make_float4(f01.x, f01.y, f23.x, f23.y);
}
// accumulate 8 halves (uint4) * w into two float4 accumulators
__device__ __forceinline__ void addu4(float4& a0, float4& a1, const uint4 u, float w) {
    float2 f0 = __half22float2(*(const __half2*)&u.x);
    float2 f1 = __half22float2(*(const __half2*)&u.y);
    float2 f2 = __half22float2(*(const __half2*)&u.z);
    float2 f3 = __half22float2(*(const __half2*)&u.w);
    a0.x += f0.x * w; a0.y += f0.y * w; a0.z += f1.x * w; a0.w += f1.y * w;
    a1.x += f2.x * w; a1.y += f2.y * w; a1.z += f3.x * w; a1.w += f3.y * w;
}

// ---------------- init + hist fused ----------------
__global__ void init_hist_kernel(const float* __restrict__ x, const int* __restrict__ ei, int E) {
    int i = blockIdx.x * blockDim.x + threadIdx.x;
    if (i < NN * HID / 2) {
        float2 f = ((const float2*)x)[i];
        ((__half2*)d_xh)[i] = __floats2half2_rn(f.x, f.y);
    }
    if (i < HID) { d_colsum[i] = 0.f; d_colsum2[i] = 0.f; }
    if (i < GG * HID) d_hg[i] = 0.f;
    if (i < 2) d_flag[i] = 0;
    int e = i * 4;
    if (e + 4 <= E) {
        int c0 = ei[E + e], c1 = ei[E + e + 1], c2 = ei[E + e + 2], c3 = ei[E + e + 3];
        atomicAdd(&d_hist[c0], 1);
        atomicAdd(&d_hist[c1], 1);
        atomicAdd(&d_hist[c2], 1);
        atomicAdd(&d_hist[c3], 1);
    } else {
        for (; e < E; e++) atomicAdd(&d_hist[ei[E + e]], 1);
    }
}

// single-block scan; consumes AND re-zeroes d_hist; writes sentinel d_off[NN]
__global__ void scan_kernel() {
    __shared__ int wsum[32];
    const int CH = NH / 1024;  // 16
    int tid = threadIdx.x;
    int lane = tid & 31, wid = tid >> 5;
    int local[CH];
    int4 raw[CH / 4];
#pragma unroll
    for (int q = 0; q < CH / 4; q++) raw[q] = ((const int4*)d_hist)[tid * (CH / 4) + q];
    int4 z4 = make_int4(0, 0, 0, 0);
#pragma unroll
    for (int q = 0; q < CH / 4; q++) ((int4*)d_hist)[tid * (CH / 4) + q] = z4;
#pragma unroll
    for (int q = 0; q < CH / 4; q++) {
        local[q * 4 + 0] = raw[q].x;
        local[q * 4 + 1] = raw[q].y;
        local[q * 4 + 2] = raw[q].z;
        local[q * 4 + 3] = raw[q].w;
    }
    int tot = 0;
#pragma unroll
    for (int j = 0; j < CH; j++) tot += local[j];
    int inc = tot;
#pragma unroll
    for (int o = 1; o < 32; o <<= 1) {
        int v = __shfl_up_sync(0xffffffff, inc, o);
        if (lane >= o) inc += v;
    }
    if (lane == 31) wsum[wid] = inc;
    __syncthreads();
    if (wid == 0) {
        int v = wsum[lane];
        int iv = v;
#pragma unroll
        for (int o = 1; o < 32; o <<= 1) {
            int u = __shfl_up_sync(0xffffffff, iv, o);
            if (lane >= o) iv += u;
        }
        wsum[lane] = iv - v;
    }
    __syncthreads();
    int run = wsum[wid] + (inc - tot);
    int base = tid * CH;
#pragma unroll
    for (int j = 0; j < CH; j++) {
        int idx = base + j;
        if (idx < NN) {
            d_off[idx] = run;
            d_cur[idx] = run;
        }
        run += local[j];
    }
    if (tid == 1023) d_off[NN] = run;
}

__global__ void scatter_kernel(const int* __restrict__ ei, int E) {
    int e = (blockIdx.x * blockDim.x + threadIdx.x) * 4;
    if (e + 4 <= E) {
        int c0 = ei[E + e], c1 = ei[E + e + 1], c2 = ei[E + e + 2], c3 = ei[E + e + 3];
        int r0 = ei[e], r1 = ei[e + 1], r2 = ei[e + 2], r3 = ei[e + 3];
        int p0 = atomicAdd(&d_cur[c0], 1);
        int p1 = atomicAdd(&d_cur[c1], 1);
        int p2 = atomicAdd(&d_cur[c2], 1);
        int p3 = atomicAdd(&d_cur[c3], 1);
        d_rows[p0] = r0;
        d_rows[p1] = r1;
        d_rows[p2] = r2;
        d_rows[p3] = r3;
    } else {
        for (; e < E; e++) {
            int p = atomicAdd(&d_cur[ei[E + e]], 1);
            d_rows[p] = ei[e];
        }
    }
}

// ---------------- aggregation: warp per node, 2 edges in flight via half-warps, uint4 gathers ----------------
// lanes 0-15 (half 0) and 16-31 (half 1) each cover the full 256B row (16 x uint4).
template<int LAYER>
__global__ void __launch_bounds__(256) agg_kernel() {
    const uint4* base = (LAYER == 0) ? d_xh : d_hh;
    int node = (blockIdx.x * blockDim.x + threadIdx.x) >> 5;
    int lane = threadIdx.x & 31;
    if (node >= NN) return;
    int start = d_off[node];
    int deg = d_off[node + 1] - start;
    int half = lane >> 4;
    int sub = lane & 15;
    float4 a0 = make_float4(0.f, 0.f, 0.f, 0.f);
    float4 a1 = a0, c0 = a0, c1 = a0;
    if (half == 0) {   // self contribution once
        float ws = (LAYER == 0) ? 1.f : d_w[node];
        addu4(a0, a1, base[node * 16 + sub], ws);
    }
    int e = 0;
    for (; e + 4 <= deg; e += 4) {   // 4 edges per iter: 2 per half-warp
        int i0 = d_rows[start + e + half * 2 + 0];
        int i1 = d_rows[start + e + half * 2 + 1];
        float w0 = (LAYER == 0) ? 1.f : d_w[i0];
        float w1 = (LAYER == 0) ? 1.f : d_w[i1];
        uint4 u0 = base[i0 * 16 + sub];
        uint4 u1 = base[i1 * 16 + sub];
        addu4(a0, a1, u0, w0);
        addu4(c0, c1, u1, w1);
    }
    for (; e + 2 <= deg; e += 2) {   // 2 edges: 1 per half
        int i0 = d_rows[start + e + half];
        float w0 = (LAYER == 0) ? 1.f : d_w[i0];
        addu4(a0, a1, base[i0 * 16 + sub], w0);
    }
    if (e < deg) {                   // final odd edge: half 0 only
        if (half == 0) {
            int i0 = d_rows[start + e];
            float w0 = (LAYER == 0) ? 1.f : d_w[i0];
            addu4(a0, a1, base[i0 * 16 + sub], w0);
        }
    }
    f4acc(a0, c0);
    f4acc(a1, c1);
    // cross-half combine
    a0.x += __shfl_xor_sync(0xffffffff, a0.x, 16);
    a0.y += __shfl_xor_sync(0xffffffff, a0.y, 16);
    a0.z += __shfl_xor_sync(0xffffffff, a0.z, 16);
    a0.w += __shfl_xor_sync(0xffffffff, a0.w, 16);
    a1.x += __shfl_xor_sync(0xffffffff, a1.x, 16);
    a1.y += __shfl_xor_sync(0xffffffff, a1.y, 16);
    a1.z += __shfl_xor_sync(0xffffffff, a1.z, 16);
    a1.w += __shfl_xor_sync(0xffffffff, a1.w, 16);
    if (half == 0) {
        ((float4*)d_z)[node * 32 + sub * 2 + 0] = a0;   // cols 8*sub .. 8*sub+3
        ((float4*)d_z)[node * 32 + sub * 2 + 1] = a1;   // cols 8*sub+4 .. 8*sub+7
    }
}

// ---------------- fused MLP: y=z@W1+b1 -> BN stats (grid spin) -> relu(bn(y))@W2+b2 -> relu -> fp16 h, attn s ----
__global__ void __launch_bounds__(256, 2)
mlp_kernel(const float* __restrict__ W1, const float* __restrict__ b1,
           const float* __restrict__ g, const float* __restrict__ be, float invn,
           const float* __restrict__ W2, const float* __restrict__ b2,
           const float* __restrict__ aw, const float* __restrict__ ab, int flagIdx) {
    __shared__ float As[64][HID];
    __shared__ float Bs[32][HID];
    int tid = threadIdx.x;
    int tx = tid & 15, ty = tid >> 4;
    int row0 = blockIdx.x * 64;

#pragma unroll
    for (int l = 0; l < 8; l++) {
        int fid = tid + l * 256;
        int r = fid >> 5, c4 = fid & 31;
        float4 v = make_float4(0.f, 0.f, 0.f, 0.f);
        if (row0 + r < NN) v = *(const float4*)(d_z + (size_t)(row0 + r) * HID + c4 * 4);
        *(float4*)&As[r][c4 * 4] = v;
    }
    float acc[4][8];
    {
        float bj[8];
#pragma unroll
        for (int jj = 0; jj < 8; jj++) bj[jj] = b1[tx * 8 + jj];
#pragma unroll
        for (int ii = 0; ii < 4; ii++)
#pragma unroll
            for (int jj = 0; jj < 8; jj++) acc[ii][jj] = bj[jj];
    }

#pragma unroll
    for (int kc = 0; kc < 4; kc++) {
        __syncthreads();
#pragma unroll
        for (int l = 0; l < 4; l++) {
            int fid = tid + l * 256;
            int r = fid >> 5, c4 = fid & 31;
            *(float4*)&Bs[r][c4 * 4] = *(const float4*)(W1 + (size_t)(kc * 32 + r) * HID + c4 * 4);
        }
        __syncthreads();
#pragma unroll 4
        for (int kk = 0; kk < 32; kk++) {
            int k = kc * 32 + kk;
            float aa[4];
#pragma unroll
            for (int ii = 0; ii < 4; ii++) aa[ii] = As[ty * 4 + ii][k];
            float4 b0 = *(const float4*)&Bs[kk][tx * 8];
            float4 b1v = *(const float4*)&Bs[kk][tx * 8 + 4];
            float bb[8] = {b0.x, b0.y, b0.z, b0.w, b1v.x, b1v.y, b1v.z, b1v.w};
#pragma unroll
            for (int ii = 0; ii < 4; ii++)
#pragma unroll
                for (int jj = 0; jj < 8; jj++) acc[ii][jj] += aa[ii] * bb[jj];
        }
    }

    // ---- BN stats ----
    {
        float p[8], q[8];
#pragma unroll
        for (int jj = 0; jj < 8; jj++) { p[jj] = 0.f; q[jj] = 0.f; }
#pragma unroll
        for (int ii = 0; ii < 4; ii++) {
            int r = row0 + ty * 4 + ii;
            if (r < NN) {
#pragma unroll
                for (int jj = 0; jj < 8; jj++) {
                    float v = acc[ii][jj];
                    p[jj] += v;
                    q[jj] += v * v;
                }
            }
        }
        float* red = &Bs[0][0];
        __syncthreads();
#pragma unroll
        for (int jj = 0; jj < 8; jj++) red[ty * HID + tx * 8 + jj] = p[jj];
        __syncthreads();
        if (tid < HID) {
            float sv = 0.f;
#pragma unroll
            for (int t = 0; t < 16; t++) sv += red[t * HID + tid];
            atomicAdd(&d_colsum[tid], sv);
        }
        __syncthreads();
#pragma unroll
        for (int jj = 0; jj < 8; jj++) red[ty * HID + tx * 8 + jj] = q[jj];
        __syncthreads();
        if (tid < HID) {
            float sv = 0.f;
#pragma unroll
            for (int t = 0; t < 16; t++) sv += red[t * HID + tid];
            atomicAdd(&d_colsum2[tid], sv);
        }
    }

    // ---- grid barrier: BN scale/shift ----
    __threadfence();
    __syncthreads();
    if (tid == 0) {
        unsigned t = atomicInc(&d_ticket, gridDim.x - 1);
        *(int*)&Bs[0][0] = (t == gridDim.x - 1);
    }
    __syncthreads();
    if (*(int*)&Bs[0][0]) {
        if (tid < HID) {
            float m = d_colsum[tid] * invn;
            float var = d_colsum2[tid] * invn - m * m;
            float rs = rsqrtf(var + BN_EPS);
            float sc = g[tid] * rs;
            d_scale[tid] = sc;
            d_shift[tid] = be[tid] - m * sc;
            d_colsum[tid] = 0.f;
            d_colsum2[tid] = 0.f;
        }
        __syncthreads();
        if (tid == 0) {
            __threadfence();
            atomicExch(&d_flag[flagIdx], 1);
        }
    }
    if (tid == 0) {
        while (atomicAdd(&d_flag[flagIdx], 0) == 0) __nanosleep(64);
    }
    __syncthreads();
    __threadfence();

    // ---- apply BN+relu, stage y' into As ----
    {
        float scj[8], shj[8];
#pragma unroll
        for (int jj = 0; jj < 8; jj++) {
            scj[jj] = d_scale[tx * 8 + jj];
            shj[jj] = d_shift[tx * 8 + jj];
        }
        __syncthreads();
#pragma unroll
        for (int ii = 0; ii < 4; ii++)
#pragma unroll
            for (int jj = 0; jj < 8; jj++)
                As[ty * 4 + ii][tx * 8 + jj] = fmaxf(acc[ii][jj] * scj[jj] + shj[jj], 0.f);
    }
    float awj[8];
    {
        float bj[8];
#pragma unroll
        for (int jj = 0; jj < 8; jj++) { bj[jj] = b2[tx * 8 + jj]; awj[jj] = aw[tx * 8 + jj]; }
#pragma unroll
        for (int ii = 0; ii < 4; ii++)
#pragma unroll
            for (int jj = 0; jj < 8; jj++) acc[ii][jj] = bj[jj];
    }

#pragma unroll
    for (int kc = 0; kc < 4; kc++) {
        __syncthreads();
#pragma unroll
        for (int l = 0; l < 4; l++) {
            int fid = tid + l * 256;
            int r = fid >> 5, c4 = fid & 31;
            *(float4*)&Bs[r][c4 * 4] = *(const float4*)(W2 + (size_t)(kc * 32 + r) * HID + c4 * 4);
        }
        __syncthreads();
#pragma unroll 4
        for (int kk = 0; kk < 32; kk++) {
            int k = kc * 32 + kk;
            float aa[4];
#pragma unroll
            for (int ii = 0; ii < 4; ii++) aa[ii] = As[ty * 4 + ii][k];
            float4 b0 = *(const float4*)&Bs[kk][tx * 8];
            float4 b1v = *(const float4*)&Bs[kk][tx * 8 + 4];
            float bb[8] = {b0.x, b0.y, b0.z, b0.w, b1v.x, b1v.y, b1v.z, b1v.w};
#pragma unroll
            for (int ii = 0; ii < 4; ii++)
#pragma unroll
                for (int jj = 0; jj < 8; jj++) acc[ii][jj] += aa[ii] * bb[jj];
        }
    }

    // ---- epilogue: relu -> fp16 store + attention score ----
    float sp[4] = {0.f, 0.f, 0.f, 0.f};
#pragma unroll
    for (int ii = 0; ii < 4; ii++) {
        int r = row0 + ty * 4 + ii;
        if (r < NN) {
            float v[8];
#pragma unroll
            for (int jj = 0; jj < 8; jj++) {
                v[jj] = fmaxf(acc[ii][jj], 0.f);
                sp[ii] += v[jj] * awj[jj];
            }
            uint2 u0, u1;
            *(__half2*)&u0.x = __floats2half2_rn(v[0], v[1]);
            *(__half2*)&u0.y = __floats2half2_rn(v[2], v[3]);
            *(__half2*)&u1.x = __floats2half2_rn(v[4], v[5]);
            *(__half2*)&u1.y = __floats2half2_rn(v[6], v[7]);
            ((uint2*)d_hh)[r * 32 + tx * 2 + 0] = u0;
            ((uint2*)d_hh)[r * 32 + tx * 2 + 1] = u1;
        }
    }
    float* red = &Bs[0][0];
    __syncthreads();
#pragma unroll
    for (int ii = 0; ii < 4; ii++) red[(ty * 4 + ii) * 16 + tx] = sp[ii];
    __syncthreads();
    if (tid < 64) {
        float v = 0.f;
#pragma unroll
        for (int t = 0; t < 16; t++) v += red[tid * 16 + t];
        int r = row0 + tid;
        if (r < NN) d_s[r] = 1.f / (1.f + expf(-(v + ab[0])));
    }
}

// ---------------- tst: w[i] = s[i] * sum_{j in CSR[i]} s[j]  (warp per node) ----------------
__global__ void __launch_bounds__(256) tst_kernel() {
    int node = (blockIdx.x * blockDim.x + threadIdx.x) >> 5;
    int lane = threadIdx.x & 31;
    if (node >= NN) return;
    int start = d_off[node];
    int deg = d_off[node + 1] - start;
    float t = 0.f;
    for (int e = lane; e < deg; e += 32) t += d_s[d_rows[start + e]];
#pragma unroll
    for (int o = 16; o; o >>= 1) t += __shfl_xor_sync(0xffffffff, t, o);
    if (lane == 0) d_w[node] = d_s[node] * t;
}

// ---------------- pool: hg[batch[i]] += h[i]*w[i]  (warp per node, w inline) ----------------
__global__ void __launch_bounds__(256) tstpool_kernel(const int* __restrict__ batch) {
    int node = (blockIdx.x * blockDim.x + threadIdx.x) >> 5;
    int lane = threadIdx.x & 31;
    if (node >= NN) return;
    int start = d_off[node];
    int deg = d_off[node + 1] - start;
    float t = 0.f;
    for (int e = lane; e < deg; e += 32) t += d_s[d_rows[start + e]];
#pragma unroll
    for (int o = 16; o; o >>= 1) t += __shfl_xor_sync(0xffffffff, t, o);
    float w = d_s[node] * t;
    float4 hv = h4tof4(((const uint2*)d_hh)[node * 32 + lane]);
    int b = batch[node];
    float* dst = &d_hg[b * HID + lane * 4];
    atomicAdd(dst + 0, hv.x * w);
    atomicAdd(dst + 1, hv.y * w);
    atomicAdd(dst + 2, hv.z * w);
    atomicAdd(dst + 3, hv.w * w);
}

// ---------------- head: MLP(hg) + log_softmax, single block ----------------
__global__ void __launch_bounds__(256)
head_kernel(const float* __restrict__ w1, const float* __restrict__ b1,
            const float* __restrict__ g, const float* __restrict__ be,
            const float* __restrict__ w2, const float* __restrict__ b2,
            float* __restrict__ out) {
    __shared__ float ys[GG][HID];
    __shared__ float sc[HID], sh[HID];
    __shared__ float logits[GG * OUTC];
    int tid = threadIdx.x;

#pragma unroll
    for (int l = 0; l < 8; l++) {
        int idx = tid + l * 256;
        ((float4*)&ys[0][0])[idx] = ((const float4*)d_hg)[idx];
    }
    __syncthreads();

    int row = tid >> 2;
    int c0 = (tid & 3) * 32;
    float acc[32];
#pragma unroll
    for (int j = 0; j < 32; j++) acc[j] = b1[c0 + j];
    for (int k = 0; k < HID; k++) {
        float a = ys[row][k];
#pragma unroll
        for (int j4 = 0; j4 < 8; j4++) {
            float4 w = *(const float4*)(w1 + (size_t)k * HID + c0 + j4 * 4);
            acc[j4 * 4 + 0] += a * w.x;
            acc[j4 * 4 + 1] += a * w.y;
            acc[j4 * 4 + 2] += a * w.z;
            acc[j4 * 4 + 3] += a * w.w;
        }
    }
    __syncthreads();
#pragma unroll
    for (int j = 0; j < 32; j++) ys[row][c0 + j] = acc[j];
    __syncthreads();

    if (tid < HID) {
        float s1 = 0.f, s2 = 0.f;
#pragma unroll 8
        for (int r = 0; r < GG; r++) {
            float v = ys[r][tid];
            s1 += v;
            s2 += v * v;
        }
        float m = s1 / GG;
        float var = s2 / GG - m * m;
        float rs = rsqrtf(var + BN_EPS);
        float scale = g[tid] * rs;
        sc[tid] = scale;
        sh[tid] = be[tid] - m * scale;
    }
    __syncthreads();

    for (int idx = tid; idx < GG * OUTC; idx += 256) {
        int gr = idx / OUTC, o = idx - gr * OUTC;
        float v = b2[o];
        for (int k = 0; k < HID; k++) {
            float hv = fmaxf(ys[gr][k] * sc[k] + sh[k], 0.f);
            v += hv * w2[k * OUTC + o];
        }
        logits[idx] = v;
    }
    __syncthreads();

    if (tid < GG) {
        float mx = -1e30f;
#pragma unroll
        for (int o = 0; o < OUTC; o++) mx = fmaxf(mx, logits[tid * OUTC + o]);
        float sum = 0.f;
#pragma unroll
        for (int o = 0; o < OUTC; o++) sum += expf(logits[tid * OUTC + o] - mx);
        float ls = mx + logf(sum);
#pragma unroll
        for (int o = 0; o < OUTC; o++) out[tid * OUTC + o] = logits[tid * OUTC + o] - ls;
    }
}

// ---------------- host launch ----------------
extern "C" void kernel_launch(void* const* d_in, const int* in_sizes, int n_in,
                              void* d_out, int out_size) {
    const float* x = (const float*)d_in[0];
    const int* ei = (const int*)d_in[1];
    const int* batch = (const int*)d_in[2];
    const float* c1_w1 = (const float*)d_in[3];
    const float* c1_b1 = (const float*)d_in[4];
    const float* c1_g  = (const float*)d_in[5];
    const float* c1_be = (const float*)d_in[6];
    const float* c1_w2 = (const float*)d_in[7];
    const float* c1_b2 = (const float*)d_in[8];
    const float* a1_w  = (const float*)d_in[9];
    const float* a1_b  = (const float*)d_in[10];
    const float* c2_w1 = (const float*)d_in[11];
    const float* c2_b1 = (const float*)d_in[12];
    const float* c2_g  = (const float*)d_in[13];
    const float* c2_be = (const float*)d_in[14];
    const float* c2_w2 = (const float*)d_in[15];
    const float* c2_b2 = (const float*)d_in[16];
    const float* a2_w  = (const float*)d_in[17];
    const float* a2_b  = (const float*)d_in[18];
    const float* l_w1  = (const float*)d_in[19];
    const float* l_b1  = (const float*)d_in[20];
    const float* l_g   = (const float*)d_in[21];
    const float* l_be  = (const float*)d_in[22];
    const float* l_w2  = (const float*)d_in[23];
    const float* l_b2  = (const float*)d_in[24];
    float* out = (float*)d_out;

    int E = in_sizes[1] / 2;

    const int GEMM_GRID = (NN + 63) / 64;        // 157
    const int WARP_GRID = (NN * 32 + 255) / 256; // 1250 (warp per node)
    const int E4_GRID = ((E + 3) / 4 + 255) / 256;

    // init (+hist fused) + CSR build
    init_hist_kernel<<<(NN * HID / 2 + 255) / 256, 256>>>(x, ei, E);
    scan_kernel<<<1, 1024>>>();
    scatter_kernel<<<E4_GRID, 256>>>(ei, E);

    // GIN layer 1 (fused MLP)
    agg_kernel<0><<<WARP_GRID, 256>>>();
    mlp_kernel<<<GEMM_GRID, 256>>>(c1_w1, c1_b1, c1_g, c1_be, 1.f / NN,
                                   c1_w2, c1_b2, a1_w, a1_b, 0);
    tst_kernel<<<WARP_GRID, 256>>>();

    // GIN layer 2
    agg_kernel<1><<<WARP_GRID, 256>>>();
    mlp_kernel<<<GEMM_GRID, 256>>>(c2_w1, c2_b1, c2_g, c2_be, 1.f / NN,
                                   c2_w2, c2_b2, a2_w, a2_b, 1);
    tstpool_kernel<<<WARP_GRID, 256>>>(batch);

    // head
    head_kernel<<<1, 256>>>(l_w1, l_b1, l_g, l_be, l_w2, l_b2, out);
}